// round 15
// baseline (speedup 1.0000x reference)
#include <cuda_runtime.h>

// Algebraic feature expansion:
//   out[r, 0:16]    = x[r, :]
//   out[r, 16:136]  = all pair products  x[i]*x[j],       i<j   (lexicographic)
//   out[r, 136:696] = all triple products x[i]*x[j]*x[k], i<j<k (lexicographic)
//
// R11 base (scalar ring emitter, __stcs flush) + PHASE-ALIGNED STORES:
// row stride 2784B = 96 mod 128, so fixed-column chunks give 128B store spans
// that straddle two lines for 3/4 of rows. Row r instead flushes chunks at
// column offset o_r = 8*(r mod 4): then 96*r + 4*o_r = 0 mod 128 and EVERY
// chunk store is a single aligned 128B line (heads of width 8/16/24 exactly
// fill each row's first partial line). Flush events every 8 emitted columns,
// each storing the 8 rows whose phase completes a chunk there.

#define N_COLS    16
#define OUT_COLS  696          // 16 + 120 + 560
#define BLOCK     256
#define PAD       33           // ring row stride: (r*33 + slot) % 32 = (r+slot)%32 -> conflict-free

__global__ __launch_bounds__(BLOCK)
void algebraic_kernel(const float* __restrict__ x, float* __restrict__ out) {
    __shared__ float sh[(BLOCK / 32) * 32 * PAD];

    const int lane  = threadIdx.x & 31;
    const int warp  = threadIdx.x >> 5;
    const int row   = blockIdx.x * BLOCK + threadIdx.x;      // this thread's row
    const int wrow0 = blockIdx.x * BLOCK + (warp << 5);      // first row of this warp

    // Load the 16-element row as 4x float4.
    float v[N_COLS];
    {
        const float4* xr = reinterpret_cast<const float4*>(x + (size_t)row * N_COLS);
        float4 a0 = xr[0], a1 = xr[1], a2 = xr[2], a3 = xr[3];
        v[0]  = a0.x; v[1]  = a0.y; v[2]  = a0.z; v[3]  = a0.w;
        v[4]  = a1.x; v[5]  = a1.y; v[6]  = a1.z; v[7]  = a1.w;
        v[8]  = a2.x; v[9]  = a2.y; v[10] = a2.z; v[11] = a2.w;
        v[12] = a3.x; v[13] = a3.y; v[14] = a3.z; v[15] = a3.w;
    }

    float* s      = sh + warp * (32 * PAD);   // this warp's 32x32 ring tile
    float* myslot = s + lane * PAD;           // this thread's ring row
    float* outw   = out + (size_t)wrow0 * OUT_COLS;

    int pos = 0;      // columns emitted so far (constant-folds under full unroll)

    // Flush event at t = pos (multiple of 8). Phase o = t mod 32 selects rows
    // r with r mod 4 == o/8. t < 32 -> head flush [0, o); else chunk [t-32, t).
    // All stores are single aligned 128B lines (or a line-interior head).
#define FLUSH_EVENT(t)                                                        \
    do {                                                                      \
        const int o_  = (t) & 31;                                             \
        const int rb_ = o_ >> 3;                                              \
        __syncwarp();                                                         \
        if ((t) < 32) {                                                       \
            if (lane < o_) {                                                  \
                _Pragma("unroll")                                             \
                for (int m_ = 0; m_ < 8; ++m_) {                              \
                    const int r_ = (m_ << 2) + rb_;                           \
                    __stcs(outw + r_ * OUT_COLS + lane, s[r_ * PAD + lane]);  \
                }                                                             \
            }                                                                 \
        } else {                                                              \
            const int col_  = (t) - 32 + lane;                                \
            const int slot_ = (o_ + lane) & 31;                               \
            _Pragma("unroll")                                                 \
            for (int m_ = 0; m_ < 8; ++m_) {                                  \
                const int r_ = (m_ << 2) + rb_;                               \
                __stcs(outw + r_ * OUT_COLS + col_, s[r_ * PAD + slot_]);     \
            }                                                                 \
        }                                                                     \
        __syncwarp();                                                         \
    } while (0)

#define EMIT(val)                                   \
    do {                                            \
        myslot[pos & 31] = (val);                   \
        ++pos;                                      \
        if ((pos & 7) == 0) FLUSH_EVENT(pos);       \
    } while (0)

    // ---- singles: columns 0..15 ----
#pragma unroll
    for (int i = 0; i < N_COLS; ++i) {
        EMIT(v[i]);
    }

    // ---- pairs: columns 16..135, lexicographic (i<j) ----
#pragma unroll
    for (int i = 0; i < N_COLS; ++i) {
#pragma unroll
        for (int j = i + 1; j < N_COLS; ++j) {
            EMIT(v[i] * v[j]);
        }
    }

    // ---- triples: columns 136..695, lexicographic (i<j<k) ----
#pragma unroll
    for (int i = 0; i < N_COLS; ++i) {
#pragma unroll
        for (int j = i + 1; j < N_COLS; ++j) {
            float p = v[i] * v[j];
#pragma unroll
            for (int k = j + 1; k < N_COLS; ++k) {
                EMIT(p * v[k]);
            }
        }
    }

    // pos == 696: last event (t=696, phase 24) already flushed [664,696) for
    // r%4==3. Remaining tails (all single-line, aligned bases):
    //   phase 0 rows: cols [672,696) width 24, slot = lane      (672%32 == 0)
    //   phase 1 rows: cols [680,696) width 16, slot = 8 + lane
    //   phase 2 rows: cols [688,696) width  8, slot = 16 + lane
    __syncwarp();
#define TAIL(rb_, cst_, width_)                                               \
    do {                                                                      \
        if (lane < (width_)) {                                                \
            const int col_  = (cst_) + lane;                                  \
            const int slot_ = ((cst_) + lane) & 31;                           \
            _Pragma("unroll")                                                 \
            for (int m_ = 0; m_ < 8; ++m_) {                                  \
                const int r_ = (m_ << 2) + (rb_);                             \
                __stcs(outw + r_ * OUT_COLS + col_, s[r_ * PAD + slot_]);     \
            }                                                                 \
        }                                                                     \
    } while (0)
    TAIL(0, 672, 24);
    TAIL(1, 680, 16);
    TAIL(2, 688, 8);
#undef TAIL
#undef EMIT
#undef FLUSH_EVENT
}

extern "C" void kernel_launch(void* const* d_in, const int* in_sizes, int n_in,
                              void* d_out, int out_size) {
    const float* x = (const float*)d_in[0];
    float* out = (float*)d_out;
    const int batch = in_sizes[0] / N_COLS;   // 262144
    const int grid = (batch + BLOCK - 1) / BLOCK;
    algebraic_kernel<<<grid, BLOCK>>>(x, out);
}